// round 16
// baseline (speedup 1.0000x reference)
#include <cuda_runtime.h>
#include <cuda_bf16.h>
#include <cstdint>

// ---- problem dims ----
#define Bv   8
#define Tv   1024
#define Dv   512
#define Hv   8
#define HDv  64
#define D2v  1024

// ---- scratch ----
__device__ __nv_bfloat16 g_xh[Bv * Tv * Dv];
__device__ __nv_bfloat16 g_xl[Bv * Tv * Dv];
__device__ __nv_bfloat16 g_qh[Bv * Tv * Dv];   // pre-scaled by 0.125
__device__ __nv_bfloat16 g_ql[Bv * Tv * Dv];
__device__ __nv_bfloat16 g_kh[Bv * Tv * Dv];
__device__ __nv_bfloat16 g_kl[Bv * Tv * Dv];
__device__ __nv_bfloat16 g_vh[Bv * Tv * Dv];
__device__ __nv_bfloat16 g_vl[Bv * Tv * Dv];
__device__ __nv_bfloat16 g_valh[Bv * Tv * D2v];
__device__ __nv_bfloat16 g_vall[Bv * Tv * D2v];
__device__ float g_chanP[Bv * Hv * 8 * 64 * 64];
__device__ __nv_bfloat16 g_wqh[3 * Dv * Dv];
__device__ __nv_bfloat16 g_wql[3 * Dv * Dv];
__device__ __nv_bfloat16 g_wkh[3 * Dv * Dv];
__device__ __nv_bfloat16 g_wkl[3 * Dv * Dv];
__device__ __nv_bfloat16 g_wvh[3 * Dv * Dv];
__device__ __nv_bfloat16 g_wvl[3 * Dv * Dv];
__device__ __nv_bfloat16 g_w2h[3 * D2v * Dv];
__device__ __nv_bfloat16 g_w2l[3 * D2v * Dv];

// ============================================================
// helpers (sm_80-baseline PTX only)
// ============================================================
__device__ __forceinline__ uint32_t smem_u32(const void* p) {
    uint32_t a;
    asm("{ .reg .u64 t; cvta.to.shared.u64 t, %1; cvt.u32.u64 %0, t; }"
        : "=r"(a) : "l"(p));
    return a;
}

__device__ __forceinline__ void ldsm4(uint32_t* r, uint32_t addr) {
    asm volatile("ldmatrix.sync.aligned.m8n8.x4.shared.b16 {%0,%1,%2,%3}, [%4];"
                 : "=r"(r[0]), "=r"(r[1]), "=r"(r[2]), "=r"(r[3]) : "r"(addr));
}
__device__ __forceinline__ void ldsm4t(uint32_t* r, uint32_t addr) {
    asm volatile("ldmatrix.sync.aligned.m8n8.x4.trans.shared.b16 {%0,%1,%2,%3}, [%4];"
                 : "=r"(r[0]), "=r"(r[1]), "=r"(r[2]), "=r"(r[3]) : "r"(addr));
}

__device__ __forceinline__ void mma16816(float* c, const uint32_t* a, const uint32_t* b) {
    asm volatile(
        "mma.sync.aligned.m16n8k16.row.col.f32.bf16.bf16.f32 "
        "{%0,%1,%2,%3}, {%4,%5,%6,%7}, {%8,%9}, {%0,%1,%2,%3};"
        : "+f"(c[0]), "+f"(c[1]), "+f"(c[2]), "+f"(c[3])
        : "r"(a[0]), "r"(a[1]), "r"(a[2]), "r"(a[3]), "r"(b[0]), "r"(b[1]));
}

__device__ __forceinline__ void cp16(uint32_t dst, const void* src, uint32_t n) {
    asm volatile("cp.async.cg.shared.global [%0], [%1], 16, %2;"
                 :: "r"(dst), "l"(__cvta_generic_to_global(src)), "r"(n));
}
#define CP_COMMIT  asm volatile("cp.async.commit_group;" ::: "memory")
#define CP_WAIT(n) asm volatile("cp.async.wait_group %0;" :: "n"(n) : "memory")

__device__ __forceinline__ uint32_t packbf(float lo, float hi) {
    uint32_t r;
    asm("cvt.rn.bf16x2.f32 %0, %1, %2;" : "=r"(r) : "f"(hi), "f"(lo));
    return r;
}

__device__ __forceinline__ uint32_t sm_addr(uint32_t base, int row, int col) {
    return base + (uint32_t)(row * 128 + (col ^ ((row & 7) << 4)));
}

__device__ __forceinline__ float2 rec2(uint32_t hw, uint32_t lw) {
    float2 fh = __bfloat1622float2(*(__nv_bfloat162*)&hw);
    float2 fl = __bfloat1622float2(*(__nv_bfloat162*)&lw);
    return make_float2(fh.x + fl.x, fh.y + fl.y);
}

// ============================================================
// fused transform: input split + all weight repack/split
// ============================================================
#define W1SZ (3 * Dv * Dv)
#define W2SZ (3 * D2v * Dv)
#define NXV  (Bv * Tv * Dv)

__global__ void prep_all(const float* __restrict__ x,
                         const float* __restrict__ w11, const float* __restrict__ w12,
                         const float* __restrict__ w13, const float* __restrict__ w2,
                         __nv_bfloat16* __restrict__ xh, __nv_bfloat16* __restrict__ xl,
                         __nv_bfloat16* __restrict__ wqh, __nv_bfloat16* __restrict__ wql,
                         __nv_bfloat16* __restrict__ wkh, __nv_bfloat16* __restrict__ wkl,
                         __nv_bfloat16* __restrict__ wvh, __nv_bfloat16* __restrict__ wvl,
                         __nv_bfloat16* __restrict__ w2h, __nv_bfloat16* __restrict__ w2l) {
    int idx = blockIdx.x * 256 + threadIdx.x;
    if (idx < NXV) {
        float v = x[idx];
        __nv_bfloat16 h = __float2bfloat16(v);
        xh[idx] = h;
        xl[idx] = __float2bfloat16(v - __bfloat162float(h));
        return;
    }
    idx -= NXV;
    if (idx < 3 * W1SZ) {
        int which = idx / W1SZ;
        int r = idx - which * W1SZ;
        const float* w = (which == 0) ? w11 : (which == 1) ? w12 : w13;
        __nv_bfloat16* hi = (which == 0) ? wqh : (which == 1) ? wkh : wvh;
        __nv_bfloat16* lo = (which == 0) ? wql : (which == 1) ? wkl : wvl;
        int kk = r % (3 * Dv);
        int co = r / (3 * Dv);
        int tap = kk / Dv;
        int ci  = kk - tap * Dv;
        float v = w[((size_t)co * Dv + ci) * 3 + tap];
        __nv_bfloat16 h = __float2bfloat16(v);
        hi[r] = h;
        lo[r] = __float2bfloat16(v - __bfloat162float(h));
    } else {
        int r = idx - 3 * W1SZ;
        if (r >= W2SZ) return;
        int kk = r % (3 * D2v);
        int co = r / (3 * D2v);
        int tap = kk / D2v;
        int ci  = kk - tap * D2v;
        float v = w2[((size_t)co * D2v + ci) * 3 + tap];
        __nv_bfloat16 h = __float2bfloat16(v);
        w2h[r] = h;
        w2l[r] = __float2bfloat16(v - __bfloat162float(h));
    }
}

// ============================================================
// conv1d(k=3,'same') + bias + ReLU via mma.sync bf16x3.
// CTA tile 128(t) x 64(co), 128 threads, 2 CTAs/SM. (R13 proven)
// ============================================================
#define ST3        49152
#define SMEM_TOT3  (2 * ST3)

template <int CIN, bool TRIPLE>
__global__ __launch_bounds__(128, 2)
void conv_mma3(const __nv_bfloat16* __restrict__ Xh, const __nv_bfloat16* __restrict__ Xl,
               const __nv_bfloat16* __restrict__ Wh0, const __nv_bfloat16* __restrict__ Wl0,
               const __nv_bfloat16* __restrict__ Wh1, const __nv_bfloat16* __restrict__ Wl1,
               const __nv_bfloat16* __restrict__ Wh2, const __nv_bfloat16* __restrict__ Wl2,
               const float* __restrict__ bias0, const float* __restrict__ bias1,
               const float* __restrict__ bias2,
               __nv_bfloat16* __restrict__ Yh0, __nv_bfloat16* __restrict__ Yl0,
               __nv_bfloat16* __restrict__ Yh1, __nv_bfloat16* __restrict__ Yl1,
               __nv_bfloat16* __restrict__ Yh2, __nv_bfloat16* __restrict__ Yl2,
               float* __restrict__ Yf) {
    extern __shared__ __align__(1024) char sm[];
    const uint32_t smb = smem_u32(sm);
    const int tid = threadIdx.x;
    const int b     = TRIPLE ? (blockIdx.z & 7) : blockIdx.z;
    const int which = TRIPLE ? (blockIdx.z >> 3) : 0;
    const int t0 = blockIdx.x * 128;
    const int n0 = blockIdx.y * 64;
    constexpr int KTOT = 3 * CIN;
    constexpr int C = KTOT / 64;

    const __nv_bfloat16* Wh = (which == 0) ? Wh0 : (which == 1) ? Wh1 : Wh2;
    const __nv_bfloat16* Wl = (which == 0) ? Wl0 : (which == 1) ? Wl1 : Wl2;
    const float* bias = (which == 0) ? bias0 : (which == 1) ? bias1 : bias2;

    const int lane = tid & 31, wid = tid >> 5;
    const int wm = wid & 1, wn = wid >> 1;
    const int rr = lane & 7, tt = lane >> 3;
    const int arow = wm * 64 + (tt & 1) * 8 + rr;
    const int acol = (tt >> 1) * 16;
    const int brow = wn * 32 + (tt >> 1) * 8 + rr;
    const int bcol = (tt & 1) * 16;

    float acc[4][4][4] = {};

    auto stage = [&](int c, int st) {
        const int kb  = c * 64;
        const int tap = kb / CIN;
        const int cb  = kb - tap * CIN;
        const int dt  = tap - 1;
        uint32_t base = smb + st * ST3;
        #pragma unroll
        for (int j = 0; j < 16; j++) {
            int half = j >> 3;
            int u = tid + (j & 7) * 128;
            int r = u >> 3, cu = u & 7;
            uint32_t sw = (uint32_t)(r * 128 + ((cu * 16) ^ ((r & 7) << 4)));
            int tg = t0 + r + dt;
            uint32_t ok = (tg >= 0 && tg < Tv) ? 16u : 0u;
            int tc = min(max(tg, 0), Tv - 1);
            const __nv_bfloat16* src = (half ? Xl : Xh) +
                ((size_t)(b * Tv + tc) * CIN + cb + cu * 8);
            cp16(base + half * 16384 + sw, src, ok);
        }
        #pragma unroll
        for (int j = 0; j < 8; j++) {
            int half = j >> 2;
            int u = tid + (j & 3) * 128;
            int r = u >> 3, cu = u & 7;
            uint32_t sw = (uint32_t)(r * 128 + ((cu * 16) ^ ((r & 7) << 4)));
            const __nv_bfloat16* src = (half ? Wl : Wh) +
                ((size_t)(n0 + r) * KTOT + kb + cu * 8);
            cp16(base + 32768 + half * 8192 + sw, src, 16u);
        }
    };

    auto compute = [&](int st) {
        const uint32_t ah_b = smb + st * ST3;
        const uint32_t al_b = ah_b + 16384;
        const uint32_t bh_b = ah_b + 32768;
        const uint32_t bl_b = ah_b + 40960;
        #pragma unroll
        for (int ks = 0; ks < 4; ks++) {
            uint32_t Ah[4][4], Al[4][4], Bh[4][2], Bl[4][2];
            #pragma unroll
            for (int mi = 0; mi < 4; mi++) {
                ldsm4(Ah[mi], sm_addr(ah_b, arow + mi * 16, acol + ks * 32));
                ldsm4(Al[mi], sm_addr(al_b, arow + mi * 16, acol + ks * 32));
            }
            #pragma unroll
            for (int jp = 0; jp < 2; jp++) {
                uint32_t r4[4];
                ldsm4(r4, sm_addr(bh_b, brow + jp * 16, bcol + ks * 32));
                Bh[2 * jp][0] = r4[0]; Bh[2 * jp][1] = r4[1];
                Bh[2 * jp + 1][0] = r4[2]; Bh[2 * jp + 1][1] = r4[3];
                ldsm4(r4, sm_addr(bl_b, brow + jp * 16, bcol + ks * 32));
                Bl[2 * jp][0] = r4[0]; Bl[2 * jp][1] = r4[1];
                Bl[2 * jp + 1][0] = r4[2]; Bl[2 * jp + 1][1] = r4[3];
            }
            #pragma unroll
            for (int mi = 0; mi < 4; mi++)
                #pragma unroll
                for (int nj = 0; nj < 4; nj++)
                    mma16816(acc[mi][nj], Ah[mi], Bh[nj]);
            #pragma unroll
            for (int mi = 0; mi < 4; mi++)
                #pragma unroll
                for (int nj = 0; nj < 4; nj++)
                    mma16816(acc[mi][nj], Al[mi], Bh[nj]);
            #pragma unroll
            for (int mi = 0; mi < 4; mi++)
                #pragma unroll
                for (int nj = 0; nj < 4; nj++)
                    mma16816(acc[mi][nj], Ah[mi], Bl[nj]);
        }
    };

    stage(0, 0);
    CP_COMMIT;
    for (int c = 0; c < C; c++) {
        if (c + 1 < C) { stage(c + 1, (c + 1) & 1); CP_COMMIT; CP_WAIT(1); }
        else           { CP_WAIT(0); }
        __syncthreads();
        compute(c & 1);
        __syncthreads();
    }

    const int r0 = lane >> 2;
    const int c0 = (lane & 3) * 2;
    if (TRIPLE) {
        __nv_bfloat16* Yh = (which == 0) ? Yh0 : (which == 1) ? Yh1 : Yh2;
        __nv_bfloat16* Yl = (which == 0) ? Yl0 : (which == 1) ? Yl1 : Yl2;
        const float oscale = (which == 0) ? 0.125f : 1.0f;
        #pragma unroll
        for (int mi = 0; mi < 4; mi++) {
            int mg = t0 + wm * 64 + mi * 16 + r0;
            size_t ro0 = (size_t)(b * Tv + mg) * Dv;
            size_t ro1 = (size_t)(b * Tv + mg + 8) * Dv;
            #pragma unroll
            for (int nj = 0; nj < 4; nj++) {
                int ng = n0 + wn * 32 + nj * 8 + c0;
                float2 bv = *(const float2*)(bias + ng);
                float v0 = fmaxf(acc[mi][nj][0] + bv.x, 0.f) * oscale;
                float v1 = fmaxf(acc[mi][nj][1] + bv.y, 0.f) * oscale;
                float v2 = fmaxf(acc[mi][nj][2] + bv.x, 0.f) * oscale;
                float v3 = fmaxf(acc[mi][nj][3] + bv.y, 0.f) * oscale;
                float h0 = __bfloat162float(__float2bfloat16(v0));
                float h1 = __bfloat162float(__float2bfloat16(v1));
                float h2 = __bfloat162float(__float2bfloat16(v2));
                float h3 = __bfloat162float(__float2bfloat16(v3));
                *(uint32_t*)(Yh + ro0 + ng) = packbf(h0, h1);
                *(uint32_t*)(Yl + ro0 + ng) = packbf(v0 - h0, v1 - h1);
                *(uint32_t*)(Yh + ro1 + ng) = packbf(h2, h3);
                *(uint32_t*)(Yl + ro1 + ng) = packbf(v2 - h2, v3 - h3);
            }
        }
    } else {
        #pragma unroll
        for (int mi = 0; mi < 4; mi++) {
            int mg = t0 + wm * 64 + mi * 16 + r0;
            float* y0 = Yf + (size_t)(b * Tv + mg) * Dv;
            float* y1 = Yf + (size_t)(b * Tv + mg + 8) * Dv;
            #pragma unroll
            for (int nj = 0; nj < 4; nj++) {
                int ng = n0 + wn * 32 + nj * 8 + c0;
                float2 bv = *(const float2*)(bias + ng);
                *(float2*)(y0 + ng) = make_float2(fmaxf(acc[mi][nj][0] + bv.x, 0.f),
                                                  fmaxf(acc[mi][nj][1] + bv.y, 0.f));
                *(float2*)(y1 + ng) = make_float2(fmaxf(acc[mi][nj][2] + bv.x, 0.f),
                                                  fmaxf(acc[mi][nj][3] + bv.y, 0.f));
            }
        }
    }
}

// ============================================================
// Fused: time-wise flash attention (R13-proven interleaved MMA)
// + chan partial GEMM blocks.
// grid (24, H, B): x<16 = attention (64 q rows); x>=16 = chan partial z=x-16.
// ============================================================
#define AT_Q     16384
#define AT_STAGE 32768
#define AT_SMEM  (AT_Q + 2 * AT_STAGE)

__global__ __launch_bounds__(128, 2)
void attn_time_fused(const __nv_bfloat16* __restrict__ Qh, const __nv_bfloat16* __restrict__ Ql,
                     const __nv_bfloat16* __restrict__ Kh, const __nv_bfloat16* __restrict__ Kl,
                     const __nv_bfloat16* __restrict__ Vh, const __nv_bfloat16* __restrict__ Vl,
                     __nv_bfloat16* __restrict__ Oh, __nv_bfloat16* __restrict__ Ol,
                     float* __restrict__ Pout) {
    extern __shared__ __align__(1024) char sm[];
    const uint32_t smb = smem_u32(sm);
    const int tid = threadIdx.x, lane = tid & 31, wid = tid >> 5;

    // ---------- chan partial branch (fma-only; overlaps tensor work) ----------
    if (blockIdx.x >= 16) {
        float* Qs = (float*)sm;
        float* Ks = Qs + 2048;
        const int h = blockIdx.y, b = blockIdx.z, z = blockIdx.x - 16;
        const int tx = tid & 15, ty = tid >> 4;      // 16 x 8

        float acc[8][4] = {};
        for (int t0 = z * 128; t0 < z * 128 + 128; t0 += 32) {
            __syncthreads();
            #pragma unroll
            for (int j2 = 0; j2 < 8; j2++) {
                int j = tid + j2 * 128;
                int r = j >> 5;
                int c2 = (j & 31) * 2;
                size_t base = (size_t)(b * Tv + t0 + r) * Dv + h * HDv + c2;
                float2 fq = rec2(*(const uint32_t*)(Qh + base), *(const uint32_t*)(Ql + base));
                float2 fk = rec2(*(const uint32_t*)(Kh + base), *(const uint32_t*)(Kl + base));
                Qs[r * 64 + c2] = fq.x; Qs[r * 64 + c2 + 1] = fq.y;
                Ks[r * 64 + c2] = fk.x; Ks[r * 64 + c2 + 1] = fk.y;
            }
            __syncthreads();
            #pragma unroll
            for (int r = 0; r < 32; r++) {
                float av[8];
                #pragma unroll
                for (int i = 0; i < 8; i += 4)
                    *(float4*)&av[i] = *(const float4*)&Qs[r * 64 + ty * 8 + i];
                float4 w4 = *(const float4*)&Ks[r * 64 + (tx << 2)];
                float wv[4] = {w4.x, w4.y, w4.z, w4.w};
                #pragma unroll
                for (int i = 0; i < 8; i++)
                    #pragma unroll
                    for (int jj = 0; jj < 4; jj++)
                        acc[i][jj] += av[i] * wv[jj];
            }
        }
        float* pp = Pout + ((size_t)(b * Hv + h) * 8 + z) * 4096;
        #pragma unroll
        for (int i = 0; i < 8; i++)
            #pragma unroll
            for (int jj = 0; jj < 4; jj++)
                pp[(ty * 8 + i) * 64 + (tx << 2) + jj] = acc[i][jj];
        return;
    }

    // ---------- attention branch (byte-identical logic to R13/R15) ----------
    const int b = blockIdx.z, h = blockIdx.y, t0 = blockIdx.x * 64;
    const int rr = lane & 7, tt = lane >> 3;

    #pragma unroll
    for (int j = 0; j < 8; j++) {
        int u = tid + j * 128;
        int half = u >> 9;
        int w = u & 511;
        int r = w >> 3, cu = w & 7;
        uint32_t sw = (uint32_t)(r * 128 + ((cu * 16) ^ ((r & 7) << 4)));
        const __nv_bfloat16* src = (half ? Ql : Qh) +
            ((size_t)(b * Tv + t0 + r) * Dv + h * HDv + cu * 8);
        cp16(smb + half * 8192 + sw, src, 16u);
    }
    CP_COMMIT;

    auto stageKV = [&](int kc, int st) {
        uint32_t base = smb + AT_Q + st * AT_STAGE;
        #pragma unroll
        for (int j = 0; j < 16; j++) {
            int u = tid + j * 128;
            int arr = u >> 9;
            int w = u & 511;
            int r = w >> 3, cu = w & 7;
            uint32_t sw = (uint32_t)(r * 128 + ((cu * 16) ^ ((r & 7) << 4)));
            const __nv_bfloat16* src;
            if (arr == 0) src = Kh; else if (arr == 1) src = Kl;
            else if (arr == 2) src = Vh; else src = Vl;
            src += (size_t)(b * Tv + kc * 64 + r) * Dv + h * HDv + cu * 8;
            cp16(base + arr * 8192 + sw, src, 16u);
        }
    };
    stageKV(0, 0);
    CP_COMMIT;

    uint32_t qh[4][4], ql[4][4];
    float o[8][4] = {};
    float m0 = -1e30f, m1 = -1e30f, l0 = 0.f, l1 = 0.f;

    const int arow = wid * 16 + (tt & 1) * 8 + rr;
    const int acolb = (tt >> 1) * 16;
    const int brow = (tt >> 1) * 8 + rr;
    const int bcolb = (tt & 1) * 16;
    const int vrow = (tt & 1) * 8 + rr;
    const int vcolb = (tt >> 1) * 16;

    for (int c = 0; c < Tv / 64; c++) {
        if (c + 1 < Tv / 64) { stageKV(c + 1, (c + 1) & 1); CP_COMMIT; CP_WAIT(1); }
        else                 { CP_WAIT(0); }
        __syncthreads();
        if (c == 0) {
            #pragma unroll
            for (int ks = 0; ks < 4; ks++) {
                ldsm4(qh[ks], sm_addr(smb,        arow, acolb + ks * 32));
                ldsm4(ql[ks], sm_addr(smb + 8192, arow, acolb + ks * 32));
            }
        }
        const uint32_t kbase = smb + AT_Q + (c & 1) * AT_STAGE;
        float accs[8][4] = {};
        #pragma unroll
        for (int ks = 0; ks < 4; ks++) {
            #pragma unroll
            for (int jp = 0; jp < 4; jp++) {
                uint32_t kh4[4], kl4[4];
                ldsm4(kh4, sm_addr(kbase,        brow + jp * 16, bcolb + ks * 32));
                ldsm4(kl4, sm_addr(kbase + 8192, brow + jp * 16, bcolb + ks * 32));
                mma16816(accs[2 * jp],     qh[ks], kh4);
                mma16816(accs[2 * jp + 1], qh[ks], kh4 + 2);
                mma16816(accs[2 * jp],     ql[ks], kh4);
                mma16816(accs[2 * jp + 1], ql[ks], kh4 + 2);
                mma16816(accs[2 * jp],     qh[ks], kl4);
                mma16816(accs[2 * jp + 1], qh[ks], kl4 + 2);
            }
        }
        float mx0 = accs[0][0], mx1 = accs[0][2];
        #pragma unroll
        for (int nj = 0; nj < 8; nj++) {
            mx0 = fmaxf(mx0, fmaxf(accs[nj][0], accs[nj][1]));
            mx1 = fmaxf(mx1, fmaxf(accs[nj][2], accs[nj][3]));
        }
        mx0 = fmaxf(mx0, __shfl_xor_sync(0xffffffffu, mx0, 1));
        mx0 = fmaxf(mx0, __shfl_xor_sync(0xffffffffu, mx0, 2));
        mx1 = fmaxf(mx1, __shfl_xor_sync(0xffffffffu, mx1, 1));
        mx1 = fmaxf(mx1, __shfl_xor_sync(0xffffffffu, mx1, 2));
        float nm0 = fmaxf(m0, mx0), nm1 = fmaxf(m1, mx1);
        float al0 = __expf(m0 - nm0), al1 = __expf(m1 - nm1);
        m0 = nm0; m1 = nm1;
        l0 *= al0; l1 *= al1;
        #pragma unroll
        for (int nj = 0; nj < 8; nj++) {
            o[nj][0] *= al0; o[nj][1] *= al0;
            o[nj][2] *= al1; o[nj][3] *= al1;
        }
        uint32_t pkh[8][2], pkl[8][2];
        #pragma unroll
        for (int nj = 0; nj < 8; nj++) {
            float p0 = __expf(accs[nj][0] - m0), p1 = __expf(accs[nj][1] - m0);
            float p2 = __expf(accs[nj][2] - m1), p3 = __expf(accs[nj][3] - m1);
            l0 += p0 + p1; l1 += p2 + p3;
            float h0 = __bfloat162float(__float2bfloat16(p0));
            float h1 = __bfloat162float(__float2bfloat16(p1));
            float h2 = __bfloat162float(__float2bfloat16(p2));
            float h3 = __bfloat162float(__float2bfloat16(p3));
            pkh[nj][0] = packbf(h0, h1);
            pkh[nj][1] = packbf(h2, h3);
            pkl[nj][0] = packbf(p0 - h0, p1 - h1);
            pkl[nj][1] = packbf(p2 - h2, p3 - h3);
        }
        const uint32_t vbase = kbase + 16384;
        #pragma unroll
        for (int ks = 0; ks < 4; ks++) {
            uint32_t pah[4] = {pkh[2 * ks][0], pkh[2 * ks][1],
                               pkh[2 * ks + 1][0], pkh[2 * ks + 1][1]};
            uint32_t pal[4] = {pkl[2 * ks][0], pkl[2 * ks][1],
                               pkl[2 * ks + 1][0], pkl[2 * ks + 1][1]};
            #pragma unroll
            for (int dg = 0; dg < 4; dg++) {
                uint32_t vh4[4], vl4[4];
                ldsm4t(vh4, sm_addr(vbase,        vrow + ks * 16, vcolb + dg * 32));
                ldsm4t(vl4, sm_addr(vbase + 8192, vrow + ks * 16, vcolb + dg * 32));
                mma16816(o[2 * dg],     pah, vh4);
                mma16816(o[2 * dg + 1], pah, vh4 + 2);
                mma16816(o[2 * dg],     pal, vh4);
                mma16816(o[2 * dg + 1], pal, vh4 + 2);
                mma16816(o[2 * dg],     pah, vl4);
                mma16816(o[2 * dg + 1], pah, vl4 + 2);
            }
        }
        __syncthreads();
    }

    l0 += __shfl_xor_sync(0xffffffffu, l0, 1);
    l0 += __shfl_xor_sync(0xffffffffu, l0, 2);
    l1 += __shfl_xor_sync(0xffffffffu, l1, 1);
    l1 += __shfl_xor_sync(0xffffffffu, l1, 2);
    float i0 = 1.f / l0, i1 = 1.f / l1;

    const int r0 = lane >> 2, c0 = (lane & 3) * 2;
    int tr = t0 + wid * 16 + r0;
    size_t ob0 = (size_t)(b * Tv + tr) * D2v + h * HDv;
    size_t ob1 = ob0 + (size_t)8 * D2v;
    #pragma unroll
    for (int nj = 0; nj < 8; nj++) {
        int d = nj * 8 + c0;
        float v0 = o[nj][0] * i0, v1 = o[nj][1] * i0;
        float v2 = o[nj][2] * i1, v3 = o[nj][3] * i1;
        float h0 = __bfloat162float(__float2bfloat16(v0));
        float h1 = __bfloat162float(__float2bfloat16(v1));
        float h2 = __bfloat162float(__float2bfloat16(v2));
        float h3 = __bfloat162float(__float2bfloat16(v3));
        *(uint32_t*)(Oh + ob0 + d) = packbf(h0, h1);
        *(uint32_t*)(Ol + ob0 + d) = packbf(v0 - h0, v1 - h1);
        *(uint32_t*)(Oh + ob1 + d) = packbf(h2, h3);
        *(uint32_t*)(Ol + ob1 + d) = packbf(v2 - h2, v3 - h3);
    }
}

// ============================================================
// Channel attention part 2 WITH folded reduce+softmax (R15 proven).
// ============================================================
__global__ __launch_bounds__(256) void attn_chan_av(
    const __nv_bfloat16* __restrict__ Vh, const __nv_bfloat16* __restrict__ Vl,
    const float* __restrict__ Pin,
    __nv_bfloat16* __restrict__ VALh, __nv_bfloat16* __restrict__ VALl)
{
    __shared__ float As[64][65];
    __shared__ float Vst[64 * 68];

    int h = blockIdx.x, b = blockIdx.y, zc = blockIdx.z;
    int tid = threadIdx.x;
    int tx = tid & 15, ty = tid >> 4;

    const float* pp = Pin + (size_t)(b * Hv + h) * 8 * 4096;
    #pragma unroll
    for (int j2 = 0; j2 < 16; j2++) {
        int j = tid + j2 * 256;
        float s = 0.f;
        #pragma unroll
        for (int z = 0; z < 8; z++) s += pp[z * 4096 + j];
        As[j >> 6][j & 63] = s * 0.25f;
    }
    __syncthreads();
    if (tid < 64) {
        float mx = -1e30f;
        #pragma unroll 8
        for (int d = 0; d < 64; d++) mx = fmaxf(mx, As[tid][d]);
        float sum = 0.f;
        #pragma unroll 8
        for (int d = 0; d < 64; d++) { float e = __expf(As[tid][d] - mx); As[tid][d] = e; sum += e; }
        float inv = 1.f / sum;
        #pragma unroll 8
        for (int d = 0; d < 64; d++) As[tid][d] *= inv;
    }

    for (int sub = 0; sub < 4; sub++) {
        int t20 = zc * 256 + sub * 64;
        __syncthreads();
        #pragma unroll
        for (int j2 = 0; j2 < 8; j2++) {
            int j = tid + j2 * 256;
            int r = j >> 5;
            int c2 = (j & 31) * 2;
            size_t base = (size_t)(b * Tv + t20 + r) * Dv + h * HDv + c2;
            float2 fv = rec2(*(const uint32_t*)(Vh + base), *(const uint32_t*)(Vl + base));
            Vst[(c2 + 0) * 68 + r] = fv.x;
            Vst[(c2 + 1) * 68 + r] = fv.y;
        }
        __syncthreads();
        float o[4][4] = {};
        #pragma unroll
        for (int d = 0; d < 64; d++) {
            float a0 = As[(ty << 2) + 0][d];
            float a1 = As[(ty << 2) + 1][d];
            float a2 = As[(ty << 2) + 2][d];
            float a3 = As[(ty << 2) + 3][d];
            float4 vv = *(const float4*)&Vst[d * 68 + (tx << 2)];
            o[0][0] += a0 * vv.x; o[0][1] += a0 * vv.y; o[0][2] += a0 * vv.z; o[0][3] += a0 * vv.w;
            o[1][0] += a1 * vv.x; o[1][1] += a1 * vv.y; o[1][2] += a1 * vv.z; o[1][3] += a1 * vv.w;
            o[2][0] += a2 * vv.x; o[2][1] += a2 * vv.y; o[2][2] += a2 * vv.z; o[2][3] += a2 * vv.w;
            o[3][0] += a3 * vv.x; o[3][1] += a3 * vv.y; o[3][2] += a3 * vv.z; o[3][3] += a3 * vv.w;
        }
        #pragma unroll
        for (int i = 0; i < 4; i++) {
            int c = (ty << 2) + i;
            #pragma unroll
            for (int jj = 0; jj < 4; jj++) {
                int t2 = t20 + (tx << 2) + jj;
                int t_out = c * 16 + (t2 >> 6);
                int col = ((t2 & 63) << 3) + h;
                size_t idx = (size_t)(b * Tv + t_out) * D2v + Dv + col;
                float v = o[i][jj];
                __nv_bfloat16 hh = __float2bfloat16(v);
                VALh[idx] = hh;
                VALl[idx] = __float2bfloat16(v - __bfloat162float(hh));
            }
        }
    }
}

// ============================================================
// launch
// ============================================================
extern "C" void kernel_launch(void* const* d_in, const int* in_sizes, int n_in,
                              void* d_out, int out_size) {
    const float* x   = (const float*)d_in[0];
    const float* w11 = (const float*)d_in[1];
    const float* b11 = (const float*)d_in[2];
    const float* w12 = (const float*)d_in[3];
    const float* b12 = (const float*)d_in[4];
    const float* w13 = (const float*)d_in[5];
    const float* b13 = (const float*)d_in[6];
    const float* w2  = (const float*)d_in[7];
    const float* b2  = (const float*)d_in[8];
    float* out = (float*)d_out;

    __nv_bfloat16 *xh, *xl, *qh, *ql, *kh, *kl, *vh, *vl, *valh, *vall;
    __nv_bfloat16 *wqh, *wql, *wkh, *wkl, *wvh, *wvl, *w2h, *w2l;
    float *chanP;
    cudaGetSymbolAddress((void**)&xh,   g_xh);
    cudaGetSymbolAddress((void**)&xl,   g_xl);
    cudaGetSymbolAddress((void**)&qh,   g_qh);
    cudaGetSymbolAddress((void**)&ql,   g_ql);
    cudaGetSymbolAddress((void**)&kh,   g_kh);
    cudaGetSymbolAddress((void**)&kl,   g_kl);
    cudaGetSymbolAddress((void**)&vh,   g_vh);
    cudaGetSymbolAddress((void**)&vl,   g_vl);
    cudaGetSymbolAddress((void**)&valh, g_valh);
    cudaGetSymbolAddress((void**)&vall, g_vall);
    cudaGetSymbolAddress((void**)&chanP, g_chanP);
    cudaGetSymbolAddress((void**)&wqh,  g_wqh);
    cudaGetSymbolAddress((void**)&wql,  g_wql);
    cudaGetSymbolAddress((void**)&wkh,  g_wkh);
    cudaGetSymbolAddress((void**)&wkl,  g_wkl);
    cudaGetSymbolAddress((void**)&wvh,  g_wvh);
    cudaGetSymbolAddress((void**)&wvl,  g_wvl);
    cudaGetSymbolAddress((void**)&w2h,  g_w2h);
    cudaGetSymbolAddress((void**)&w2l,  g_w2l);

    cudaFuncSetAttribute(conv_mma3<Dv, true>,
                         cudaFuncAttributeMaxDynamicSharedMemorySize, SMEM_TOT3);
    cudaFuncSetAttribute(conv_mma3<D2v, false>,
                         cudaFuncAttributeMaxDynamicSharedMemorySize, SMEM_TOT3);
    cudaFuncSetAttribute(attn_time_fused,
                         cudaFuncAttributeMaxDynamicSharedMemorySize, AT_SMEM);

    int ptot = NXV + 3 * W1SZ + W2SZ;
    prep_all<<<(ptot + 255) / 256, 256>>>(x, w11, w12, w13, w2,
                                          xh, xl, wqh, wql, wkh, wkl, wvh, wvl,
                                          w2h, w2l);

    conv_mma3<Dv, true><<<dim3(Tv / 128, Dv / 64, 3 * Bv), 128, SMEM_TOT3>>>(
        xh, xl,
        wqh, wql, wkh, wkl, wvh, wvl,
        b11, b12, b13,
        qh, ql, kh, kl, vh, vl,
        nullptr);

    attn_time_fused<<<dim3(24, Hv, Bv), 128, AT_SMEM>>>(qh, ql, kh, kl, vh, vl,
                                                        valh, vall, chanP);
    attn_chan_av<<<dim3(Hv, Bv, 4), 256>>>(vh, vl, chanP, valh, vall);

    conv_mma3<D2v, false><<<dim3(Tv / 128, Dv / 64, Bv), 128, SMEM_TOT3>>>(
        valh, vall,
        w2h, w2l, nullptr, nullptr, nullptr, nullptr,
        b2, nullptr, nullptr,
        nullptr, nullptr, nullptr, nullptr, nullptr, nullptr,
        out);
}

// round 17
// speedup vs baseline: 1.0105x; 1.0105x over previous
#include <cuda_runtime.h>
#include <cuda_bf16.h>
#include <cstdint>

// ---- problem dims ----
#define Bv   8
#define Tv   1024
#define Dv   512
#define Hv   8
#define HDv  64
#define D2v  1024

// ---- scratch ----
__device__ __nv_bfloat16 g_xh[Bv * Tv * Dv];
__device__ __nv_bfloat16 g_xl[Bv * Tv * Dv];
__device__ __nv_bfloat16 g_qh[Bv * Tv * Dv];   // pre-scaled by 0.125
__device__ __nv_bfloat16 g_ql[Bv * Tv * Dv];
__device__ __nv_bfloat16 g_kh[Bv * Tv * Dv];
__device__ __nv_bfloat16 g_kl[Bv * Tv * Dv];
__device__ __nv_bfloat16 g_vh[Bv * Tv * Dv];
__device__ __nv_bfloat16 g_vl[Bv * Tv * Dv];
__device__ __nv_bfloat16 g_valh[Bv * Tv * D2v];
__device__ __nv_bfloat16 g_vall[Bv * Tv * D2v];
__device__ float g_chanP[Bv * Hv * 8 * 64 * 64];
__device__ __nv_bfloat16 g_wqh[3 * Dv * Dv];
__device__ __nv_bfloat16 g_wql[3 * Dv * Dv];
__device__ __nv_bfloat16 g_wkh[3 * Dv * Dv];
__device__ __nv_bfloat16 g_wkl[3 * Dv * Dv];
__device__ __nv_bfloat16 g_wvh[3 * Dv * Dv];
__device__ __nv_bfloat16 g_wvl[3 * Dv * Dv];
__device__ __nv_bfloat16 g_w2h[3 * D2v * Dv];
__device__ __nv_bfloat16 g_w2l[3 * D2v * Dv];

// ============================================================
// helpers (sm_80-baseline PTX only)
// ============================================================
__device__ __forceinline__ uint32_t smem_u32(const void* p) {
    uint32_t a;
    asm("{ .reg .u64 t; cvta.to.shared.u64 t, %1; cvt.u32.u64 %0, t; }"
        : "=r"(a) : "l"(p));
    return a;
}

__device__ __forceinline__ void ldsm4(uint32_t* r, uint32_t addr) {
    asm volatile("ldmatrix.sync.aligned.m8n8.x4.shared.b16 {%0,%1,%2,%3}, [%4];"
                 : "=r"(r[0]), "=r"(r[1]), "=r"(r[2]), "=r"(r[3]) : "r"(addr));
}
__device__ __forceinline__ void ldsm4t(uint32_t* r, uint32_t addr) {
    asm volatile("ldmatrix.sync.aligned.m8n8.x4.trans.shared.b16 {%0,%1,%2,%3}, [%4];"
                 : "=r"(r[0]), "=r"(r[1]), "=r"(r[2]), "=r"(r[3]) : "r"(addr));
}

__device__ __forceinline__ void mma16816(float* c, const uint32_t* a, const uint32_t* b) {
    asm volatile(
        "mma.sync.aligned.m16n8k16.row.col.f32.bf16.bf16.f32 "
        "{%0,%1,%2,%3}, {%4,%5,%6,%7}, {%8,%9}, {%0,%1,%2,%3};"
        : "+f"(c[0]), "+f"(c[1]), "+f"(c[2]), "+f"(c[3])
        : "r"(a[0]), "r"(a[1]), "r"(a[2]), "r"(a[3]), "r"(b[0]), "r"(b[1]));
}

__device__ __forceinline__ void cp16(uint32_t dst, const void* src, uint32_t n) {
    asm volatile("cp.async.cg.shared.global [%0], [%1], 16, %2;"
                 :: "r"(dst), "l"(__cvta_generic_to_global(src)), "r"(n));
}
#define CP_COMMIT  asm volatile("cp.async.commit_group;" ::: "memory")
#define CP_WAIT(n) asm volatile("cp.async.wait_group %0;" :: "n"(n) : "memory")

__device__ __forceinline__ uint32_t packbf(float lo, float hi) {
    uint32_t r;
    asm("cvt.rn.bf16x2.f32 %0, %1, %2;" : "=r"(r) : "f"(hi), "f"(lo));
    return r;
}

__device__ __forceinline__ uint32_t sm_addr(uint32_t base, int row, int col) {
    return base + (uint32_t)(row * 128 + (col ^ ((row & 7) << 4)));
}

__device__ __forceinline__ float2 rec2(uint32_t hw, uint32_t lw) {
    float2 fh = __bfloat1622float2(*(__nv_bfloat162*)&hw);
    float2 fl = __bfloat1622float2(*(__nv_bfloat162*)&lw);
    return make_float2(fh.x + fl.x, fh.y + fl.y);
}

// ============================================================
// fused transform: input split + all weight repack/split
// ============================================================
#define W1SZ (3 * Dv * Dv)
#define W2SZ (3 * D2v * Dv)
#define NXV  (Bv * Tv * Dv)

__global__ void prep_all(const float* __restrict__ x,
                         const float* __restrict__ w11, const float* __restrict__ w12,
                         const float* __restrict__ w13, const float* __restrict__ w2,
                         __nv_bfloat16* __restrict__ xh, __nv_bfloat16* __restrict__ xl,
                         __nv_bfloat16* __restrict__ wqh, __nv_bfloat16* __restrict__ wql,
                         __nv_bfloat16* __restrict__ wkh, __nv_bfloat16* __restrict__ wkl,
                         __nv_bfloat16* __restrict__ wvh, __nv_bfloat16* __restrict__ wvl,
                         __nv_bfloat16* __restrict__ w2h, __nv_bfloat16* __restrict__ w2l) {
    int idx = blockIdx.x * 256 + threadIdx.x;
    if (idx < NXV) {
        float v = x[idx];
        __nv_bfloat16 h = __float2bfloat16(v);
        xh[idx] = h;
        xl[idx] = __float2bfloat16(v - __bfloat162float(h));
        return;
    }
    idx -= NXV;
    if (idx < 3 * W1SZ) {
        int which = idx / W1SZ;
        int r = idx - which * W1SZ;
        const float* w = (which == 0) ? w11 : (which == 1) ? w12 : w13;
        __nv_bfloat16* hi = (which == 0) ? wqh : (which == 1) ? wkh : wvh;
        __nv_bfloat16* lo = (which == 0) ? wql : (which == 1) ? wkl : wvl;
        int kk = r % (3 * Dv);
        int co = r / (3 * Dv);
        int tap = kk / Dv;
        int ci  = kk - tap * Dv;
        float v = w[((size_t)co * Dv + ci) * 3 + tap];
        __nv_bfloat16 h = __float2bfloat16(v);
        hi[r] = h;
        lo[r] = __float2bfloat16(v - __bfloat162float(h));
    } else {
        int r = idx - 3 * W1SZ;
        if (r >= W2SZ) return;
        int kk = r % (3 * D2v);
        int co = r / (3 * D2v);
        int tap = kk / D2v;
        int ci  = kk - tap * D2v;
        float v = w2[((size_t)co * D2v + ci) * 3 + tap];
        __nv_bfloat16 h = __float2bfloat16(v);
        w2h[r] = h;
        w2l[r] = __float2bfloat16(v - __bfloat162float(h));
    }
}

// ============================================================
// conv1d(k=3,'same') + bias + ReLU via mma.sync bf16x3.
// CTA tile 128(t) x 64(co), 128 threads, 2 CTAs/SM. (R13 proven)
// ============================================================
#define ST3        49152
#define SMEM_TOT3  (2 * ST3)

template <int CIN, bool TRIPLE>
__global__ __launch_bounds__(128, 2)
void conv_mma3(const __nv_bfloat16* __restrict__ Xh, const __nv_bfloat16* __restrict__ Xl,
               const __nv_bfloat16* __restrict__ Wh0, const __nv_bfloat16* __restrict__ Wl0,
               const __nv_bfloat16* __restrict__ Wh1, const __nv_bfloat16* __restrict__ Wl1,
               const __nv_bfloat16* __restrict__ Wh2, const __nv_bfloat16* __restrict__ Wl2,
               const float* __restrict__ bias0, const float* __restrict__ bias1,
               const float* __restrict__ bias2,
               __nv_bfloat16* __restrict__ Yh0, __nv_bfloat16* __restrict__ Yl0,
               __nv_bfloat16* __restrict__ Yh1, __nv_bfloat16* __restrict__ Yl1,
               __nv_bfloat16* __restrict__ Yh2, __nv_bfloat16* __restrict__ Yl2,
               float* __restrict__ Yf) {
    extern __shared__ __align__(1024) char sm[];
    const uint32_t smb = smem_u32(sm);
    const int tid = threadIdx.x;
    const int b     = TRIPLE ? (blockIdx.z & 7) : blockIdx.z;
    const int which = TRIPLE ? (blockIdx.z >> 3) : 0;
    const int t0 = blockIdx.x * 128;
    const int n0 = blockIdx.y * 64;
    constexpr int KTOT = 3 * CIN;
    constexpr int C = KTOT / 64;

    const __nv_bfloat16* Wh = (which == 0) ? Wh0 : (which == 1) ? Wh1 : Wh2;
    const __nv_bfloat16* Wl = (which == 0) ? Wl0 : (which == 1) ? Wl1 : Wl2;
    const float* bias = (which == 0) ? bias0 : (which == 1) ? bias1 : bias2;

    const int lane = tid & 31, wid = tid >> 5;
    const int wm = wid & 1, wn = wid >> 1;
    const int rr = lane & 7, tt = lane >> 3;
    const int arow = wm * 64 + (tt & 1) * 8 + rr;
    const int acol = (tt >> 1) * 16;
    const int brow = wn * 32 + (tt >> 1) * 8 + rr;
    const int bcol = (tt & 1) * 16;

    float acc[4][4][4] = {};

    auto stage = [&](int c, int st) {
        const int kb  = c * 64;
        const int tap = kb / CIN;
        const int cb  = kb - tap * CIN;
        const int dt  = tap - 1;
        uint32_t base = smb + st * ST3;
        #pragma unroll
        for (int j = 0; j < 16; j++) {
            int half = j >> 3;
            int u = tid + (j & 7) * 128;
            int r = u >> 3, cu = u & 7;
            uint32_t sw = (uint32_t)(r * 128 + ((cu * 16) ^ ((r & 7) << 4)));
            int tg = t0 + r + dt;
            uint32_t ok = (tg >= 0 && tg < Tv) ? 16u : 0u;
            int tc = min(max(tg, 0), Tv - 1);
            const __nv_bfloat16* src = (half ? Xl : Xh) +
                ((size_t)(b * Tv + tc) * CIN + cb + cu * 8);
            cp16(base + half * 16384 + sw, src, ok);
        }
        #pragma unroll
        for (int j = 0; j < 8; j++) {
            int half = j >> 2;
            int u = tid + (j & 3) * 128;
            int r = u >> 3, cu = u & 7;
            uint32_t sw = (uint32_t)(r * 128 + ((cu * 16) ^ ((r & 7) << 4)));
            const __nv_bfloat16* src = (half ? Wl : Wh) +
                ((size_t)(n0 + r) * KTOT + kb + cu * 8);
            cp16(base + 32768 + half * 8192 + sw, src, 16u);
        }
    };

    auto compute = [&](int st) {
        const uint32_t ah_b = smb + st * ST3;
        const uint32_t al_b = ah_b + 16384;
        const uint32_t bh_b = ah_b + 32768;
        const uint32_t bl_b = ah_b + 40960;
        #pragma unroll
        for (int ks = 0; ks < 4; ks++) {
            uint32_t Ah[4][4], Al[4][4], Bh[4][2], Bl[4][2];
            #pragma unroll
            for (int mi = 0; mi < 4; mi++) {
                ldsm4(Ah[mi], sm_addr(ah_b, arow + mi * 16, acol + ks * 32));
                ldsm4(Al[mi], sm_addr(al_b, arow + mi * 16, acol + ks * 32));
            }
            #pragma unroll
            for (int jp = 0; jp < 2; jp++) {
                uint32_t r4[4];
                ldsm4(r4, sm_addr(bh_b, brow + jp * 16, bcol + ks * 32));
                Bh[2 * jp][0] = r4[0]; Bh[2 * jp][1] = r4[1];
                Bh[2 * jp + 1][0] = r4[2]; Bh[2 * jp + 1][1] = r4[3];
                ldsm4(r4, sm_addr(bl_b, brow + jp * 16, bcol + ks * 32));
                Bl[2 * jp][0] = r4[0]; Bl[2 * jp][1] = r4[1];
                Bl[2 * jp + 1][0] = r4[2]; Bl[2 * jp + 1][1] = r4[3];
            }
            #pragma unroll
            for (int mi = 0; mi < 4; mi++)
                #pragma unroll
                for (int nj = 0; nj < 4; nj++)
                    mma16816(acc[mi][nj], Ah[mi], Bh[nj]);
            #pragma unroll
            for (int mi = 0; mi < 4; mi++)
                #pragma unroll
                for (int nj = 0; nj < 4; nj++)
                    mma16816(acc[mi][nj], Al[mi], Bh[nj]);
            #pragma unroll
            for (int mi = 0; mi < 4; mi++)
                #pragma unroll
                for (int nj = 0; nj < 4; nj++)
                    mma16816(acc[mi][nj], Ah[mi], Bl[nj]);
        }
    };

    stage(0, 0);
    CP_COMMIT;
    for (int c = 0; c < C; c++) {
        if (c + 1 < C) { stage(c + 1, (c + 1) & 1); CP_COMMIT; CP_WAIT(1); }
        else           { CP_WAIT(0); }
        __syncthreads();
        compute(c & 1);
        __syncthreads();
    }

    const int r0 = lane >> 2;
    const int c0 = (lane & 3) * 2;
    if (TRIPLE) {
        __nv_bfloat16* Yh = (which == 0) ? Yh0 : (which == 1) ? Yh1 : Yh2;
        __nv_bfloat16* Yl = (which == 0) ? Yl0 : (which == 1) ? Yl1 : Yl2;
        const float oscale = (which == 0) ? 0.125f : 1.0f;
        #pragma unroll
        for (int mi = 0; mi < 4; mi++) {
            int mg = t0 + wm * 64 + mi * 16 + r0;
            size_t ro0 = (size_t)(b * Tv + mg) * Dv;
            size_t ro1 = (size_t)(b * Tv + mg + 8) * Dv;
            #pragma unroll
            for (int nj = 0; nj < 4; nj++) {
                int ng = n0 + wn * 32 + nj * 8 + c0;
                float2 bv = *(const float2*)(bias + ng);
                float v0 = fmaxf(acc[mi][nj][0] + bv.x, 0.f) * oscale;
                float v1 = fmaxf(acc[mi][nj][1] + bv.y, 0.f) * oscale;
                float v2 = fmaxf(acc[mi][nj][2] + bv.x, 0.f) * oscale;
                float v3 = fmaxf(acc[mi][nj][3] + bv.y, 0.f) * oscale;
                float h0 = __bfloat162float(__float2bfloat16(v0));
                float h1 = __bfloat162float(__float2bfloat16(v1));
                float h2 = __bfloat162float(__float2bfloat16(v2));
                float h3 = __bfloat162float(__float2bfloat16(v3));
                *(uint32_t*)(Yh + ro0 + ng) = packbf(h0, h1);
                *(uint32_t*)(Yl + ro0 + ng) = packbf(v0 - h0, v1 - h1);
                *(uint32_t*)(Yh + ro1 + ng) = packbf(h2, h3);
                *(uint32_t*)(Yl + ro1 + ng) = packbf(v2 - h2, v3 - h3);
            }
        }
    } else {
        #pragma unroll
        for (int mi = 0; mi < 4; mi++) {
            int mg = t0 + wm * 64 + mi * 16 + r0;
            float* y0 = Yf + (size_t)(b * Tv + mg) * Dv;
            float* y1 = Yf + (size_t)(b * Tv + mg + 8) * Dv;
            #pragma unroll
            for (int nj = 0; nj < 4; nj++) {
                int ng = n0 + wn * 32 + nj * 8 + c0;
                float2 bv = *(const float2*)(bias + ng);
                *(float2*)(y0 + ng) = make_float2(fmaxf(acc[mi][nj][0] + bv.x, 0.f),
                                                  fmaxf(acc[mi][nj][1] + bv.y, 0.f));
                *(float2*)(y1 + ng) = make_float2(fmaxf(acc[mi][nj][2] + bv.x, 0.f),
                                                  fmaxf(acc[mi][nj][3] + bv.y, 0.f));
            }
        }
    }
}

// ============================================================
// Time-wise flash attention via mma.sync bf16x3 (R13 proven — interleaved MMA).
// 128-thr CTA, 64 q rows, 2 CTAs/SM.
// ============================================================
#define AT_Q     16384
#define AT_STAGE 32768
#define AT_SMEM  (AT_Q + 2 * AT_STAGE)

__global__ __launch_bounds__(128, 2)
void attn_time_hmma(const __nv_bfloat16* __restrict__ Qh, const __nv_bfloat16* __restrict__ Ql,
                    const __nv_bfloat16* __restrict__ Kh, const __nv_bfloat16* __restrict__ Kl,
                    const __nv_bfloat16* __restrict__ Vh, const __nv_bfloat16* __restrict__ Vl,
                    __nv_bfloat16* __restrict__ Oh, __nv_bfloat16* __restrict__ Ol) {
    extern __shared__ __align__(1024) char sm[];
    const uint32_t smb = smem_u32(sm);
    const int tid = threadIdx.x, lane = tid & 31, wid = tid >> 5;
    const int b = blockIdx.z, h = blockIdx.y, t0 = blockIdx.x * 64;
    const int rr = lane & 7, tt = lane >> 3;

    #pragma unroll
    for (int j = 0; j < 8; j++) {
        int u = tid + j * 128;
        int half = u >> 9;
        int w = u & 511;
        int r = w >> 3, cu = w & 7;
        uint32_t sw = (uint32_t)(r * 128 + ((cu * 16) ^ ((r & 7) << 4)));
        const __nv_bfloat16* src = (half ? Ql : Qh) +
            ((size_t)(b * Tv + t0 + r) * Dv + h * HDv + cu * 8);
        cp16(smb + half * 8192 + sw, src, 16u);
    }
    CP_COMMIT;

    auto stageKV = [&](int kc, int st) {
        uint32_t base = smb + AT_Q + st * AT_STAGE;
        #pragma unroll
        for (int j = 0; j < 16; j++) {
            int u = tid + j * 128;
            int arr = u >> 9;
            int w = u & 511;
            int r = w >> 3, cu = w & 7;
            uint32_t sw = (uint32_t)(r * 128 + ((cu * 16) ^ ((r & 7) << 4)));
            const __nv_bfloat16* src;
            if (arr == 0) src = Kh; else if (arr == 1) src = Kl;
            else if (arr == 2) src = Vh; else src = Vl;
            src += (size_t)(b * Tv + kc * 64 + r) * Dv + h * HDv + cu * 8;
            cp16(base + arr * 8192 + sw, src, 16u);
        }
    };
    stageKV(0, 0);
    CP_COMMIT;

    uint32_t qh[4][4], ql[4][4];
    float o[8][4] = {};
    float m0 = -1e30f, m1 = -1e30f, l0 = 0.f, l1 = 0.f;

    const int arow = wid * 16 + (tt & 1) * 8 + rr;
    const int acolb = (tt >> 1) * 16;
    const int brow = (tt >> 1) * 8 + rr;
    const int bcolb = (tt & 1) * 16;
    const int vrow = (tt & 1) * 8 + rr;
    const int vcolb = (tt >> 1) * 16;

    for (int c = 0; c < Tv / 64; c++) {
        if (c + 1 < Tv / 64) { stageKV(c + 1, (c + 1) & 1); CP_COMMIT; CP_WAIT(1); }
        else                 { CP_WAIT(0); }
        __syncthreads();
        if (c == 0) {
            #pragma unroll
            for (int ks = 0; ks < 4; ks++) {
                ldsm4(qh[ks], sm_addr(smb,        arow, acolb + ks * 32));
                ldsm4(ql[ks], sm_addr(smb + 8192, arow, acolb + ks * 32));
            }
        }
        const uint32_t kbase = smb + AT_Q + (c & 1) * AT_STAGE;
        float accs[8][4] = {};
        #pragma unroll
        for (int ks = 0; ks < 4; ks++) {
            #pragma unroll
            for (int jp = 0; jp < 4; jp++) {
                uint32_t kh4[4], kl4[4];
                ldsm4(kh4, sm_addr(kbase,        brow + jp * 16, bcolb + ks * 32));
                ldsm4(kl4, sm_addr(kbase + 8192, brow + jp * 16, bcolb + ks * 32));
                mma16816(accs[2 * jp],     qh[ks], kh4);
                mma16816(accs[2 * jp + 1], qh[ks], kh4 + 2);
                mma16816(accs[2 * jp],     ql[ks], kh4);
                mma16816(accs[2 * jp + 1], ql[ks], kh4 + 2);
                mma16816(accs[2 * jp],     qh[ks], kl4);
                mma16816(accs[2 * jp + 1], qh[ks], kl4 + 2);
            }
        }
        float mx0 = accs[0][0], mx1 = accs[0][2];
        #pragma unroll
        for (int nj = 0; nj < 8; nj++) {
            mx0 = fmaxf(mx0, fmaxf(accs[nj][0], accs[nj][1]));
            mx1 = fmaxf(mx1, fmaxf(accs[nj][2], accs[nj][3]));
        }
        mx0 = fmaxf(mx0, __shfl_xor_sync(0xffffffffu, mx0, 1));
        mx0 = fmaxf(mx0, __shfl_xor_sync(0xffffffffu, mx0, 2));
        mx1 = fmaxf(mx1, __shfl_xor_sync(0xffffffffu, mx1, 1));
        mx1 = fmaxf(mx1, __shfl_xor_sync(0xffffffffu, mx1, 2));
        float nm0 = fmaxf(m0, mx0), nm1 = fmaxf(m1, mx1);
        float al0 = __expf(m0 - nm0), al1 = __expf(m1 - nm1);
        m0 = nm0; m1 = nm1;
        l0 *= al0; l1 *= al1;
        #pragma unroll
        for (int nj = 0; nj < 8; nj++) {
            o[nj][0] *= al0; o[nj][1] *= al0;
            o[nj][2] *= al1; o[nj][3] *= al1;
        }
        uint32_t pkh[8][2], pkl[8][2];
        #pragma unroll
        for (int nj = 0; nj < 8; nj++) {
            float p0 = __expf(accs[nj][0] - m0), p1 = __expf(accs[nj][1] - m0);
            float p2 = __expf(accs[nj][2] - m1), p3 = __expf(accs[nj][3] - m1);
            l0 += p0 + p1; l1 += p2 + p3;
            float h0 = __bfloat162float(__float2bfloat16(p0));
            float h1 = __bfloat162float(__float2bfloat16(p1));
            float h2 = __bfloat162float(__float2bfloat16(p2));
            float h3 = __bfloat162float(__float2bfloat16(p3));
            pkh[nj][0] = packbf(h0, h1);
            pkh[nj][1] = packbf(h2, h3);
            pkl[nj][0] = packbf(p0 - h0, p1 - h1);
            pkl[nj][1] = packbf(p2 - h2, p3 - h3);
        }
        const uint32_t vbase = kbase + 16384;
        #pragma unroll
        for (int ks = 0; ks < 4; ks++) {
            uint32_t pah[4] = {pkh[2 * ks][0], pkh[2 * ks][1],
                               pkh[2 * ks + 1][0], pkh[2 * ks + 1][1]};
            uint32_t pal[4] = {pkl[2 * ks][0], pkl[2 * ks][1],
                               pkl[2 * ks + 1][0], pkl[2 * ks + 1][1]};
            #pragma unroll
            for (int dg = 0; dg < 4; dg++) {
                uint32_t vh4[4], vl4[4];
                ldsm4t(vh4, sm_addr(vbase,        vrow + ks * 16, vcolb + dg * 32));
                ldsm4t(vl4, sm_addr(vbase + 8192, vrow + ks * 16, vcolb + dg * 32));
                mma16816(o[2 * dg],     pah, vh4);
                mma16816(o[2 * dg + 1], pah, vh4 + 2);
                mma16816(o[2 * dg],     pal, vh4);
                mma16816(o[2 * dg + 1], pal, vh4 + 2);
                mma16816(o[2 * dg],     pah, vl4);
                mma16816(o[2 * dg + 1], pah, vl4 + 2);
            }
        }
        __syncthreads();
    }

    l0 += __shfl_xor_sync(0xffffffffu, l0, 1);
    l0 += __shfl_xor_sync(0xffffffffu, l0, 2);
    l1 += __shfl_xor_sync(0xffffffffu, l1, 1);
    l1 += __shfl_xor_sync(0xffffffffu, l1, 2);
    float i0 = 1.f / l0, i1 = 1.f / l1;

    const int r0 = lane >> 2, c0 = (lane & 3) * 2;
    int tr = t0 + wid * 16 + r0;
    size_t ob0 = (size_t)(b * Tv + tr) * D2v + h * HDv;
    size_t ob1 = ob0 + (size_t)8 * D2v;
    #pragma unroll
    for (int nj = 0; nj < 8; nj++) {
        int d = nj * 8 + c0;
        float v0 = o[nj][0] * i0, v1 = o[nj][1] * i0;
        float v2 = o[nj][2] * i1, v3 = o[nj][3] * i1;
        float h0 = __bfloat162float(__float2bfloat16(v0));
        float h1 = __bfloat162float(__float2bfloat16(v1));
        float h2 = __bfloat162float(__float2bfloat16(v2));
        float h3 = __bfloat162float(__float2bfloat16(v3));
        *(uint32_t*)(Oh + ob0 + d) = packbf(h0, h1);
        *(uint32_t*)(Ol + ob0 + d) = packbf(v0 - h0, v1 - h1);
        *(uint32_t*)(Oh + ob1 + d) = packbf(h2, h3);
        *(uint32_t*)(Ol + ob1 + d) = packbf(v2 - h2, v3 - h3);
    }
}

// ============================================================
// Channel attention 1a: partial S sums. grid (H, B, 8). (R13 proven)
// ============================================================
__global__ __launch_bounds__(256) void chan_s_part(
    const __nv_bfloat16* __restrict__ Qh, const __nv_bfloat16* __restrict__ Ql,
    const __nv_bfloat16* __restrict__ Kh, const __nv_bfloat16* __restrict__ Kl,
    float* __restrict__ Pout)
{
    __shared__ float Qs[32 * 64];
    __shared__ float Ks[32 * 64];

    int h = blockIdx.x, b = blockIdx.y, z = blockIdx.z;
    int tid = threadIdx.x;
    int tx = tid & 15, ty = tid >> 4;

    float acc[4][4] = {};
    for (int t0 = z * 128; t0 < z * 128 + 128; t0 += 32) {
        __syncthreads();
        #pragma unroll
        for (int j2 = 0; j2 < 4; j2++) {
            int j = tid + j2 * 256;
            int r = j >> 5;
            int c2 = (j & 31) * 2;
            size_t base = (size_t)(b * Tv + t0 + r) * Dv + h * HDv + c2;
            float2 fq = rec2(*(const uint32_t*)(Qh + base), *(const uint32_t*)(Ql + base));
            float2 fk = rec2(*(const uint32_t*)(Kh + base), *(const uint32_t*)(Kl + base));
            Qs[r * 64 + c2] = fq.x; Qs[r * 64 + c2 + 1] = fq.y;
            Ks[r * 64 + c2] = fk.x; Ks[r * 64 + c2 + 1] = fk.y;
        }
        __syncthreads();
        #pragma unroll
        for (int r = 0; r < 32; r++) {
            float4 a  = *(const float4*)&Qs[r * 64 + (ty << 2)];
            float4 w4 = *(const float4*)&Ks[r * 64 + (tx << 2)];
            float av[4] = {a.x, a.y, a.z, a.w};
            float wv[4] = {w4.x, w4.y, w4.z, w4.w};
            #pragma unroll
            for (int i = 0; i < 4; i++)
                #pragma unroll
                for (int jj = 0; jj < 4; jj++)
                    acc[i][jj] += av[i] * wv[jj];
        }
    }
    float* pp = Pout + ((size_t)(b * Hv + h) * 8 + z) * 4096;
    #pragma unroll
    for (int i = 0; i < 4; i++)
        #pragma unroll
        for (int jj = 0; jj < 4; jj++)
            pp[((ty << 2) + i) * 64 + (tx << 2) + jj] = acc[i][jj];
}

// ============================================================
// Channel attention part 2 (folded reduce+softmax), 4x parallelism:
// grid (H, B, 16); each CTA handles ONE 64-t2 sub-block.
// ============================================================
__global__ __launch_bounds__(256) void attn_chan_av(
    const __nv_bfloat16* __restrict__ Vh, const __nv_bfloat16* __restrict__ Vl,
    const float* __restrict__ Pin,
    __nv_bfloat16* __restrict__ VALh, __nv_bfloat16* __restrict__ VALl)
{
    __shared__ float As[64][65];
    __shared__ float Vst[64 * 68];

    int h = blockIdx.x, b = blockIdx.y, zc = blockIdx.z;
    int tid = threadIdx.x;
    int tx = tid & 15, ty = tid >> 4;
    int t20 = zc * 64;

    // ---- folded reduce: sum 8 partials -> As ----
    const float* pp = Pin + (size_t)(b * Hv + h) * 8 * 4096;
    #pragma unroll
    for (int j2 = 0; j2 < 16; j2++) {
        int j = tid + j2 * 256;
        float s = 0.f;
        #pragma unroll
        for (int z = 0; z < 8; z++) s += pp[z * 4096 + j];
        As[j >> 6][j & 63] = s * 0.25f;   // (1/32 scale) * 8 (q pre-scaled 1/8)
    }
    // ---- stage V tile (independent of As; no sync needed yet) ----
    #pragma unroll
    for (int j2 = 0; j2 < 8; j2++) {
        int j = tid + j2 * 256;
        int r = j >> 5;
        int c2 = (j & 31) * 2;
        size_t base = (size_t)(b * Tv + t20 + r) * Dv + h * HDv + c2;
        float2 fv = rec2(*(const uint32_t*)(Vh + base), *(const uint32_t*)(Vl + base));
        Vst[(c2 + 0) * 68 + r] = fv.x;
        Vst[(c2 + 1) * 68 + r] = fv.y;
    }
    __syncthreads();
    // ---- row softmax on As ----
    if (tid < 64) {
        float mx = -1e30f;
        #pragma unroll 8
        for (int d = 0; d < 64; d++) mx = fmaxf(mx, As[tid][d]);
        float sum = 0.f;
        #pragma unroll 8
        for (int d = 0; d < 64; d++) { float e = __expf(As[tid][d] - mx); As[tid][d] = e; sum += e; }
        float inv = 1.f / sum;
        #pragma unroll 8
        for (int d = 0; d < 64; d++) As[tid][d] *= inv;
    }
    __syncthreads();

    // ---- O = A @ V^T for this 64-t2 block ----
    float o[4][4] = {};
    #pragma unroll
    for (int d = 0; d < 64; d++) {
        float a0 = As[(ty << 2) + 0][d];
        float a1 = As[(ty << 2) + 1][d];
        float a2 = As[(ty << 2) + 2][d];
        float a3 = As[(ty << 2) + 3][d];
        float4 vv = *(const float4*)&Vst[d * 68 + (tx << 2)];
        o[0][0] += a0 * vv.x; o[0][1] += a0 * vv.y; o[0][2] += a0 * vv.z; o[0][3] += a0 * vv.w;
        o[1][0] += a1 * vv.x; o[1][1] += a1 * vv.y; o[1][2] += a1 * vv.z; o[1][3] += a1 * vv.w;
        o[2][0] += a2 * vv.x; o[2][1] += a2 * vv.y; o[2][2] += a2 * vv.z; o[2][3] += a2 * vv.w;
        o[3][0] += a3 * vv.x; o[3][1] += a3 * vv.y; o[3][2] += a3 * vv.z; o[3][3] += a3 * vv.w;
    }
    #pragma unroll
    for (int i = 0; i < 4; i++) {
        int c = (ty << 2) + i;
        #pragma unroll
        for (int jj = 0; jj < 4; jj++) {
            int t2 = t20 + (tx << 2) + jj;
            int t_out = c * 16 + (t2 >> 6);
            int col = ((t2 & 63) << 3) + h;
            size_t idx = (size_t)(b * Tv + t_out) * D2v + Dv + col;
            float v = o[i][jj];
            __nv_bfloat16 hh = __float2bfloat16(v);
            VALh[idx] = hh;
            VALl[idx] = __float2bfloat16(v - __bfloat162float(hh));
        }
    }
}

// ============================================================
// launch
// ============================================================
extern "C" void kernel_launch(void* const* d_in, const int* in_sizes, int n_in,
                              void* d_out, int out_size) {
    const float* x   = (const float*)d_in[0];
    const float* w11 = (const float*)d_in[1];
    const float* b11 = (const float*)d_in[2];
    const float* w12 = (const float*)d_in[3];
    const float* b12 = (const float*)d_in[4];
    const float* w13 = (const float*)d_in[5];
    const float* b13 = (const float*)d_in[6];
    const float* w2  = (const float*)d_in[7];
    const float* b2  = (const float*)d_in[8];
    float* out = (float*)d_out;

    __nv_bfloat16 *xh, *xl, *qh, *ql, *kh, *kl, *vh, *vl, *valh, *vall;
    __nv_bfloat16 *wqh, *wql, *wkh, *wkl, *wvh, *wvl, *w2h, *w2l;
    float *chanP;
    cudaGetSymbolAddress((void**)&xh,   g_xh);
    cudaGetSymbolAddress((void**)&xl,   g_xl);
    cudaGetSymbolAddress((void**)&qh,   g_qh);
    cudaGetSymbolAddress((void**)&ql,   g_ql);
    cudaGetSymbolAddress((void**)&kh,   g_kh);
    cudaGetSymbolAddress((void**)&kl,   g_kl);
    cudaGetSymbolAddress((void**)&vh,   g_vh);
    cudaGetSymbolAddress((void**)&vl,   g_vl);
    cudaGetSymbolAddress((void**)&valh, g_valh);
    cudaGetSymbolAddress((void**)&vall, g_vall);
    cudaGetSymbolAddress((void**)&chanP, g_chanP);
    cudaGetSymbolAddress((void**)&wqh,  g_wqh);
    cudaGetSymbolAddress((void**)&wql,  g_wql);
    cudaGetSymbolAddress((void**)&wkh,  g_wkh);
    cudaGetSymbolAddress((void**)&wkl,  g_wkl);
    cudaGetSymbolAddress((void**)&wvh,  g_wvh);
    cudaGetSymbolAddress((void**)&wvl,  g_wvl);
    cudaGetSymbolAddress((void**)&w2h,  g_w2h);
    cudaGetSymbolAddress((void**)&w2l,  g_w2l);

    cudaFuncSetAttribute(conv_mma3<Dv, true>,
                         cudaFuncAttributeMaxDynamicSharedMemorySize, SMEM_TOT3);
    cudaFuncSetAttribute(conv_mma3<D2v, false>,
                         cudaFuncAttributeMaxDynamicSharedMemorySize, SMEM_TOT3);
    cudaFuncSetAttribute(attn_time_hmma,
                         cudaFuncAttributeMaxDynamicSharedMemorySize, AT_SMEM);

    int ptot = NXV + 3 * W1SZ + W2SZ;
    prep_all<<<(ptot + 255) / 256, 256>>>(x, w11, w12, w13, w2,
                                          xh, xl, wqh, wql, wkh, wkl, wvh, wvl,
                                          w2h, w2l);

    conv_mma3<Dv, true><<<dim3(Tv / 128, Dv / 64, 3 * Bv), 128, SMEM_TOT3>>>(
        xh, xl,
        wqh, wql, wkh, wkl, wvh, wvl,
        b11, b12, b13,
        qh, ql, kh, kl, vh, vl,
        nullptr);

    attn_time_hmma<<<dim3(Tv / 64, Hv, Bv), 128, AT_SMEM>>>(qh, ql, kh, kl, vh, vl,
                                                            valh, vall);
    chan_s_part<<<dim3(Hv, Bv, 8), 256>>>(qh, ql, kh, kl, chanP);
    attn_chan_av<<<dim3(Hv, Bv, 16), 256>>>(vh, vl, chanP, valh, vall);

    conv_mma3<D2v, false><<<dim3(Tv / 128, Dv / 64, Bv), 128, SMEM_TOT3>>>(
        valh, vall,
        w2h, w2l, nullptr, nullptr, nullptr, nullptr,
        b2, nullptr, nullptr,
        nullptr, nullptr, nullptr, nullptr, nullptr, nullptr,
        out);
}